// round 1
// baseline (speedup 1.0000x reference)
#include <cuda_runtime.h>

#define CB 2
#define CN 4096
#define CD 128
#define CH 4
#define CHD 32
#define CM (CB*CN)   // 8192 tokens

// ---------------- scratch (device globals; no allocation allowed) ----------
__device__ float  g_x  [CM*CD];
__device__ float  g_xn [CM*CD];
__device__ float  g_q  [CM*CD];
__device__ float  g_k  [CM*CD];
__device__ float  g_v  [CM*CD];
__device__ float  g_o  [CM*CD];
__device__ float  g_hid[CM*2*CD];
__device__ double g_part[64*2*CD];
__device__ float  g_mu [CD];
__device__ float  g_rstd[CD];
__device__ float  g_sq [CM];

// ---------------- small utility kernels ------------------------------------
__global__ void copy_kernel(const float* __restrict__ src, float* __restrict__ dst, int n) {
    int i = blockIdx.x * blockDim.x + threadIdx.x;
    if (i < n) dst[i] = src[i];
}

__global__ void sq_kernel(const float* __restrict__ pos, float* __restrict__ sqv) {
    int i = blockIdx.x * blockDim.x + threadIdx.x;
    if (i < CM) {
        float px = pos[2*i], py = pos[2*i+1];
        sqv[i] = px*px + py*py;
    }
}

// ---------------- BatchNorm (training mode over B*N rows) ------------------
__global__ void bn_stats_kernel(const float* __restrict__ x, double* __restrict__ part) {
    int d = threadIdx.x;           // 128 threads = one per feature
    int blk = blockIdx.x;          // 64 blocks, 128 rows each
    int r0 = blk * (CM / 64);
    double s = 0.0, s2 = 0.0;
    for (int r = 0; r < CM/64; ++r) {
        float v = x[(r0 + r)*CD + d];
        s  += (double)v;
        s2 += (double)v * (double)v;
    }
    part[blk*2*CD + d]      = s;
    part[blk*2*CD + CD + d] = s2;
}

__global__ void bn_finalize_kernel(const double* __restrict__ part,
                                   float* __restrict__ mu, float* __restrict__ rstd) {
    int d = threadIdx.x;
    double s = 0.0, s2 = 0.0;
    for (int b = 0; b < 64; ++b) {
        s  += part[b*2*CD + d];
        s2 += part[b*2*CD + CD + d];
    }
    double m   = s / (double)CM;
    double var = s2 / (double)CM - m*m;
    mu[d]   = (float)m;
    rstd[d] = rsqrtf((float)var + 1e-5f);
}

__global__ void bn_apply_kernel(const float* __restrict__ x,
                                const float* __restrict__ g, const float* __restrict__ b,
                                const float* __restrict__ mu, const float* __restrict__ rstd,
                                float* __restrict__ y) {
    int i = blockIdx.x * blockDim.x + threadIdx.x;
    if (i < CM*CD) {
        int d = i & (CD - 1);
        y[i] = (x[i] - mu[d]) * rstd[d] * g[d] + b[d];
    }
}

// ---------------- RoPE (layer 0 only) --------------------------------------
__global__ void rope_kernel(float* __restrict__ q, float* __restrict__ k,
                            const float* __restrict__ pos) {
    int idx = blockIdx.x * blockDim.x + threadIdx.x;   // over CM*64 pairs
    if (idx >= CM * 64) return;
    int p = idx & 63;       // pair index within feature dim
    int t = idx >> 6;       // token index (b*N + n)
    int group = p >> 5;     // which position coord (0 or 1)
    int fidx  = p & 31;     // frequency index
    float freq = 3.14159265358979324f * (float)(fidx + 1);  // 2*pi*(j+1)/PERIOD, PERIOD=2
    float ang = pos[t*2 + group] * freq;
    float sv, cv;
    sincosf(ang, &sv, &cv);
    int base = t*CD + (p << 1);
    float q0 = q[base], q1 = q[base+1];
    q[base]   = cv*q0 - sv*q1;
    q[base+1] = cv*q1 + sv*q0;
    float k0 = k[base], k1 = k[base+1];
    k[base]   = cv*k0 - sv*k1;
    k[base+1] = cv*k1 + sv*k0;
}

// ---------------- SGEMM: C = A(MxK) @ W(KxN) + bias [+resid][relu] ---------
__global__ void __launch_bounds__(256)
gemm_kernel(const float* __restrict__ A, const float* __restrict__ W,
            const float* __restrict__ bias, const float* __restrict__ resid,
            float* __restrict__ C, int M, int K, int Nout, int relu) {
    __shared__ float As[16][64];   // transposed A tile: As[k][m]
    __shared__ float Ws[16][64];   // Ws[k][n]
    int tid = threadIdx.x;
    int tx = tid & 15, ty = tid >> 4;
    int bm0 = blockIdx.x * 64, bn0 = blockIdx.y * 64;

    float acc[4][4] = {};

    int ar  = tid >> 2;            // A row within tile (0..63)
    int acq = (tid & 3) << 2;      // A col quad (0,4,8,12)
    int wr  = tid >> 4;            // W row (0..15)
    int wc  = (tid & 15) << 2;     // W col quad

    for (int k0 = 0; k0 < K; k0 += 16) {
        float4 av = *(const float4*)&A[(bm0 + ar)*K + k0 + acq];
        float4 wv = *(const float4*)&W[(k0 + wr)*Nout + bn0 + wc];
        __syncthreads();
        As[acq+0][ar] = av.x;
        As[acq+1][ar] = av.y;
        As[acq+2][ar] = av.z;
        As[acq+3][ar] = av.w;
        *(float4*)&Ws[wr][wc] = wv;
        __syncthreads();
        #pragma unroll
        for (int kk = 0; kk < 16; ++kk) {
            float4 a  = *(const float4*)&As[kk][ty << 2];
            float4 b4 = *(const float4*)&Ws[kk][tx << 2];
            float avv[4] = {a.x, a.y, a.z, a.w};
            float bvv[4] = {b4.x, b4.y, b4.z, b4.w};
            #pragma unroll
            for (int ii = 0; ii < 4; ++ii)
                #pragma unroll
                for (int jj = 0; jj < 4; ++jj)
                    acc[ii][jj] = fmaf(avv[ii], bvv[jj], acc[ii][jj]);
        }
    }

    int col = bn0 + (tx << 2);
    float4 bv = *(const float4*)&bias[col];
    #pragma unroll
    for (int ii = 0; ii < 4; ++ii) {
        int row = bm0 + (ty << 2) + ii;
        float4 r;
        r.x = acc[ii][0] + bv.x;
        r.y = acc[ii][1] + bv.y;
        r.z = acc[ii][2] + bv.z;
        r.w = acc[ii][3] + bv.w;
        if (resid) {
            float4 rv = *(const float4*)&resid[row*Nout + col];
            r.x += rv.x; r.y += rv.y; r.z += rv.z; r.w += rv.w;
        }
        if (relu) {
            r.x = fmaxf(r.x, 0.f); r.y = fmaxf(r.y, 0.f);
            r.z = fmaxf(r.z, 0.f); r.w = fmaxf(r.w, 0.f);
        }
        *(float4*)&C[row*Nout + col] = r;
    }
}

// ---------------- windowed flash attention ---------------------------------
// grid: (N/64, H, B); 64 threads, 1 query/thread; j-tiles of 128 in SMEM.
__global__ void __launch_bounds__(64)
attn_kernel(const float* __restrict__ q, const float* __restrict__ k,
            const float* __restrict__ v, const float* __restrict__ pos,
            const float* __restrict__ sqv, float* __restrict__ o) {
    __shared__ float  Ks[128][32];
    __shared__ float  Vs[128][32];
    __shared__ float2 Ps[128];
    __shared__ float  Ss[128];

    int b = blockIdx.z, h = blockIdx.y;
    int i = blockIdx.x * 64 + threadIdx.x;
    int t = b*CN + i;

    float4 qr[8];
    const float4* qp = (const float4*)&q[t*CD + h*CHD];
    #pragma unroll
    for (int u = 0; u < 8; ++u) qr[u] = qp[u];

    float2 pi  = ((const float2*)pos)[t];
    float  sqi = sqv[t];

    float m = -1e30f, l = 0.f;
    float4 acc[8];
    #pragma unroll
    for (int u = 0; u < 8; ++u) acc[u] = make_float4(0.f, 0.f, 0.f, 0.f);

    const float scale = 0.17677669529663687f;  // 1/sqrt(32)
    const float R2 = 0.0625f;                  // (WINDOW/2)^2

    for (int j0 = 0; j0 < CN; j0 += 128) {
        __syncthreads();
        #pragma unroll
        for (int rr = 0; rr < 2; ++rr) {
            int r  = threadIdx.x + rr*64;
            int tj = b*CN + j0 + r;
            const float4* kp = (const float4*)&k[tj*CD + h*CHD];
            const float4* vp = (const float4*)&v[tj*CD + h*CHD];
            #pragma unroll
            for (int u = 0; u < 8; ++u) {
                ((float4*)&Ks[r][0])[u] = kp[u];
                ((float4*)&Vs[r][0])[u] = vp[u];
            }
            Ps[r] = ((const float2*)pos)[tj];
            Ss[r] = sqv[tj];
        }
        __syncthreads();

        for (int j = 0; j < 128; ++j) {
            float2 pj = Ps[j];
            float d2 = sqi + Ss[j] - 2.f*(pi.x*pj.x + pi.y*pj.y);
            if (d2 <= R2) {
                const float4* kr = (const float4*)&Ks[j][0];
                float sA = 0.f, sB = 0.f, sC = 0.f, sD = 0.f;
                #pragma unroll
                for (int u = 0; u < 8; ++u) {
                    float4 kk4 = kr[u];
                    sA = fmaf(qr[u].x, kk4.x, sA);
                    sB = fmaf(qr[u].y, kk4.y, sB);
                    sC = fmaf(qr[u].z, kk4.z, sC);
                    sD = fmaf(qr[u].w, kk4.w, sD);
                }
                float s = ((sA + sB) + (sC + sD)) * scale;
                if (s > m) {
                    float alpha = __expf(m - s);
                    m = s;
                    l *= alpha;
                    #pragma unroll
                    for (int u = 0; u < 8; ++u) {
                        acc[u].x *= alpha; acc[u].y *= alpha;
                        acc[u].z *= alpha; acc[u].w *= alpha;
                    }
                }
                float pb = __expf(s - m);
                l += pb;
                const float4* vr = (const float4*)&Vs[j][0];
                #pragma unroll
                for (int u = 0; u < 8; ++u) {
                    float4 vv = vr[u];
                    acc[u].x = fmaf(pb, vv.x, acc[u].x);
                    acc[u].y = fmaf(pb, vv.y, acc[u].y);
                    acc[u].z = fmaf(pb, vv.z, acc[u].z);
                    acc[u].w = fmaf(pb, vv.w, acc[u].w);
                }
            }
        }
    }

    float inv = 1.f / l;
    float4* op = (float4*)&o[t*CD + h*CHD];
    #pragma unroll
    for (int u = 0; u < 8; ++u)
        op[u] = make_float4(acc[u].x*inv, acc[u].y*inv, acc[u].z*inv, acc[u].w*inv);
}

// ---------------- launch ----------------------------------------------------
extern "C" void kernel_launch(void* const* d_in, const int* in_sizes, int n_in,
                              void* d_out, int out_size) {
    const float* x    = (const float*)d_in[0];
    const float* pos  = (const float*)d_in[1];
    const float* Wq_w = (const float*)d_in[2];
    const float* Wq_b = (const float*)d_in[3];
    const float* Wk_w = (const float*)d_in[4];
    const float* Wk_b = (const float*)d_in[5];
    const float* Wv_w = (const float*)d_in[6];
    const float* Wv_b = (const float*)d_in[7];
    const float* Wo_w = (const float*)d_in[8];
    const float* Wo_b = (const float*)d_in[9];
    const float* n1_g = (const float*)d_in[10];
    const float* n1_b = (const float*)d_in[11];
    const float* n2_g = (const float*)d_in[12];
    const float* n2_b = (const float*)d_in[13];
    const float* l1_w = (const float*)d_in[14];
    const float* l1_b = (const float*)d_in[15];
    const float* l2_w = (const float*)d_in[16];
    const float* l2_b = (const float*)d_in[17];
    float* out = (float*)d_out;

    float *gx, *gxn, *gq, *gk, *gv, *go, *ghid, *gmu, *grstd, *gsq;
    double* gpart;
    cudaGetSymbolAddress((void**)&gx,    g_x);
    cudaGetSymbolAddress((void**)&gxn,   g_xn);
    cudaGetSymbolAddress((void**)&gq,    g_q);
    cudaGetSymbolAddress((void**)&gk,    g_k);
    cudaGetSymbolAddress((void**)&gv,    g_v);
    cudaGetSymbolAddress((void**)&go,    g_o);
    cudaGetSymbolAddress((void**)&ghid,  g_hid);
    cudaGetSymbolAddress((void**)&gpart, g_part);
    cudaGetSymbolAddress((void**)&gmu,   g_mu);
    cudaGetSymbolAddress((void**)&grstd, g_rstd);
    cudaGetSymbolAddress((void**)&gsq,   g_sq);

    copy_kernel<<<(CM*CD + 255)/256, 256>>>(x, gx, CM*CD);
    sq_kernel<<<(CM + 255)/256, 256>>>(pos, gsq);

    dim3 gP(CM/64, CD/64);        // 128 x 2 blocks for 128-wide outputs
    dim3 gF(CM/64, 2*CD/64);      // 128 x 4 blocks for 256-wide FFN hidden

    for (int i = 0; i < 2; ++i) {
        // --- attention block ---
        bn_stats_kernel<<<64, 128>>>(gx, gpart);
        bn_finalize_kernel<<<1, 128>>>(gpart, gmu, grstd);
        bn_apply_kernel<<<(CM*CD + 255)/256, 256>>>(gx, n1_g + i*CD, n1_b + i*CD, gmu, grstd, gxn);

        gemm_kernel<<<gP, 256>>>(gxn, Wq_w + i*CD*CD, Wq_b + i*CD, nullptr, gq, CM, CD, CD, 0);
        gemm_kernel<<<gP, 256>>>(gxn, Wk_w + i*CD*CD, Wk_b + i*CD, nullptr, gk, CM, CD, CD, 0);
        gemm_kernel<<<gP, 256>>>(gxn, Wv_w + i*CD*CD, Wv_b + i*CD, nullptr, gv, CM, CD, CD, 0);

        if (i == 0)
            rope_kernel<<<(CM*64 + 255)/256, 256>>>(gq, gk, pos);

        attn_kernel<<<dim3(CN/64, CH, CB), 64>>>(gq, gk, gv, pos, gsq, go);

        gemm_kernel<<<gP, 256>>>(go, Wo_w + i*CD*CD, Wo_b + i*CD, gx, gx, CM, CD, CD, 0);

        // --- FFN block ---
        bn_stats_kernel<<<64, 128>>>(gx, gpart);
        bn_finalize_kernel<<<1, 128>>>(gpart, gmu, grstd);
        bn_apply_kernel<<<(CM*CD + 255)/256, 256>>>(gx, n2_g + i*CD, n2_b + i*CD, gmu, grstd, gxn);

        gemm_kernel<<<gF, 256>>>(gxn, l1_w + i*CD*2*CD, l1_b + i*2*CD, nullptr, ghid, CM, CD, 2*CD, 1);

        float* dst = (i == 1) ? out : gx;
        gemm_kernel<<<gP, 256>>>(ghid, l2_w + i*2*CD*CD, l2_b + i*CD, gx, dst, CM, 2*CD, CD, 0);
    }
}

// round 3
// speedup vs baseline: 1.1752x; 1.1752x over previous
#include <cuda_runtime.h>
#include <math_constants.h>

#define CB 2
#define CN 4096
#define CD 128
#define CH 4
#define CHD 32
#define CM (CB*CN)   // 8192 tokens
#define NCELL 16     // 16x16 grid, cell size 1/16
#define NC2 (NCELL*NCELL)

// ---------------- scratch (device globals; no allocation allowed) ----------
__device__ float  g_x   [CM*CD];
__device__ float  g_xn  [CM*CD];
__device__ float  g_qkv [CM*3*CD];
__device__ float  g_o   [CM*CD];
__device__ float  g_hid [CM*2*CD];
__device__ double g_part[64*2*CD];
__device__ float  g_mu  [CD];
__device__ float  g_rstd[CD];
__device__ float  g_sq  [CM];
__device__ float  g_wqkv[CD*3*CD];
__device__ float  g_bqkv[3*CD];
// spatial binning
__device__ int g_cnt   [CB][NC2];
__device__ int g_cstart[CB][NC2+1];
__device__ int g_cursor[CB][NC2];
__device__ int g_ord   [CB][CN];
__device__ int g_cellid[CB][CN];

// ---------------- small utility kernels ------------------------------------
__global__ void copy_kernel(const float* __restrict__ src, float* __restrict__ dst, int n) {
    int i = blockIdx.x * blockDim.x + threadIdx.x;
    if (i < n) dst[i] = src[i];
}

__global__ void zero_cnt_kernel() {
    int i = threadIdx.x;
    if (i < CB*NC2) ((int*)g_cnt)[i] = 0;
}

__global__ void hist_kernel(const float* __restrict__ pos) {
    int t = blockIdx.x * blockDim.x + threadIdx.x;
    if (t >= CM) return;
    int b = t >> 12, n = t & (CN-1);
    float px = pos[2*t], py = pos[2*t+1];
    int cx = min(NCELL-1, max(0, (int)(px * NCELL)));
    int cy = min(NCELL-1, max(0, (int)(py * NCELL)));
    int c = cy*NCELL + cx;
    g_cellid[b][n] = c;
    atomicAdd(&g_cnt[b][c], 1);
    g_sq[t] = px*px + py*py;
}

__global__ void scan_kernel() {
    int b = threadIdx.x;
    if (b >= CB) return;
    int run = 0;
    for (int c = 0; c < NC2; ++c) {
        g_cstart[b][c] = run;
        g_cursor[b][c] = run;
        run += g_cnt[b][c];
    }
    g_cstart[b][NC2] = run;   // == CN
}

__global__ void scatter_kernel() {
    int t = blockIdx.x * blockDim.x + threadIdx.x;
    if (t >= CM) return;
    int b = t >> 12, n = t & (CN-1);
    int c = g_cellid[b][n];
    int r = atomicAdd(&g_cursor[b][c], 1);
    g_ord[b][r] = n;
}

// ---------------- BatchNorm (training mode over B*N rows) ------------------
__global__ void bn_stats_kernel(const float* __restrict__ x, double* __restrict__ part) {
    int d = threadIdx.x;
    int blk = blockIdx.x;
    int r0 = blk * (CM / 64);
    double s = 0.0, s2 = 0.0;
    for (int r = 0; r < CM/64; ++r) {
        float v = x[(r0 + r)*CD + d];
        s  += (double)v;
        s2 += (double)v * (double)v;
    }
    part[blk*2*CD + d]      = s;
    part[blk*2*CD + CD + d] = s2;
}

__global__ void bn_finalize_kernel(const double* __restrict__ part,
                                   float* __restrict__ mu, float* __restrict__ rstd) {
    int d = threadIdx.x;
    double s0=0, s1=0, s2=0, s3=0, q0=0, q1=0, q2=0, q3=0;
    #pragma unroll
    for (int b = 0; b < 64; b += 4) {
        s0 += part[(b+0)*2*CD + d];      q0 += part[(b+0)*2*CD + CD + d];
        s1 += part[(b+1)*2*CD + d];      q1 += part[(b+1)*2*CD + CD + d];
        s2 += part[(b+2)*2*CD + d];      q2 += part[(b+2)*2*CD + CD + d];
        s3 += part[(b+3)*2*CD + d];      q3 += part[(b+3)*2*CD + CD + d];
    }
    double s = (s0+s1)+(s2+s3);
    double sq = (q0+q1)+(q2+q3);
    double m   = s / (double)CM;
    double var = sq / (double)CM - m*m;
    mu[d]   = (float)m;
    rstd[d] = rsqrtf((float)var + 1e-5f);
}

__global__ void bn_apply_kernel(const float* __restrict__ x,
                                const float* __restrict__ g, const float* __restrict__ b,
                                const float* __restrict__ mu, const float* __restrict__ rstd,
                                float* __restrict__ y) {
    int i = blockIdx.x * blockDim.x + threadIdx.x;
    if (i < CM*CD) {
        int d = i & (CD - 1);
        y[i] = (x[i] - mu[d]) * rstd[d] * g[d] + b[d];
    }
}

// ---------------- pack QKV weights into one [128][384] matrix --------------
__global__ void pack_qkv_kernel(const float* __restrict__ Wq, const float* __restrict__ Wk,
                                const float* __restrict__ Wv,
                                const float* __restrict__ bq, const float* __restrict__ bk,
                                const float* __restrict__ bv) {
    int t = blockIdx.x * blockDim.x + threadIdx.x;
    if (t < CD*3*CD) {
        int row = t / (3*CD), col = t % (3*CD);
        int sel = col >> 7, c = col & (CD-1);
        const float* W = (sel == 0) ? Wq : (sel == 1) ? Wk : Wv;
        g_wqkv[t] = W[row*CD + c];
    }
    if (t < 3*CD) {
        int sel = t >> 7, c = t & (CD-1);
        const float* bb = (sel == 0) ? bq : (sel == 1) ? bk : bv;
        g_bqkv[t] = bb[c];
    }
}

// ---------------- RoPE (layer 0 only), qkv layout [M][384] -----------------
__global__ void rope_kernel(float* __restrict__ qkv, const float* __restrict__ pos) {
    int idx = blockIdx.x * blockDim.x + threadIdx.x;
    if (idx >= CM * 64) return;
    int p = idx & 63;
    int t = idx >> 6;
    int group = p >> 5;
    int fidx  = p & 31;
    float freq = 3.14159265358979324f * (float)(fidx + 1);
    float ang = pos[t*2 + group] * freq;
    float sv, cv;
    sincosf(ang, &sv, &cv);
    int qb = t*3*CD + (p << 1);
    float q0 = qkv[qb], q1 = qkv[qb+1];
    qkv[qb]   = cv*q0 - sv*q1;
    qkv[qb+1] = cv*q1 + sv*q0;
    int kb = qb + CD;
    float k0 = qkv[kb], k1 = qkv[kb+1];
    qkv[kb]   = cv*k0 - sv*k1;
    qkv[kb+1] = cv*k1 + sv*k0;
}

// ---------------- SGEMM: C = A(MxK) @ W(KxN) + bias [+resid][relu] ---------
__global__ void __launch_bounds__(256)
gemm_kernel(const float* __restrict__ A, const float* __restrict__ W,
            const float* __restrict__ bias, const float* __restrict__ resid,
            float* __restrict__ C, int M, int K, int Nout, int relu) {
    __shared__ float As[16][64];
    __shared__ float Ws[16][64];
    int tid = threadIdx.x;
    int tx = tid & 15, ty = tid >> 4;
    int bm0 = blockIdx.x * 64, bn0 = blockIdx.y * 64;

    float acc[4][4] = {};

    int ar  = tid >> 2;
    int acq = (tid & 3) << 2;
    int wr  = tid >> 4;
    int wc  = (tid & 15) << 2;

    for (int k0 = 0; k0 < K; k0 += 16) {
        float4 av = *(const float4*)&A[(bm0 + ar)*K + k0 + acq];
        float4 wv = *(const float4*)&W[(k0 + wr)*Nout + bn0 + wc];
        __syncthreads();
        As[acq+0][ar] = av.x;
        As[acq+1][ar] = av.y;
        As[acq+2][ar] = av.z;
        As[acq+3][ar] = av.w;
        *(float4*)&Ws[wr][wc] = wv;
        __syncthreads();
        #pragma unroll
        for (int kk = 0; kk < 16; ++kk) {
            float4 a  = *(const float4*)&As[kk][ty << 2];
            float4 b4 = *(const float4*)&Ws[kk][tx << 2];
            float avv[4] = {a.x, a.y, a.z, a.w};
            float bvv[4] = {b4.x, b4.y, b4.z, b4.w};
            #pragma unroll
            for (int ii = 0; ii < 4; ++ii)
                #pragma unroll
                for (int jj = 0; jj < 4; ++jj)
                    acc[ii][jj] = fmaf(avv[ii], bvv[jj], acc[ii][jj]);
        }
    }

    int col = bn0 + (tx << 2);
    float4 bv = *(const float4*)&bias[col];
    #pragma unroll
    for (int ii = 0; ii < 4; ++ii) {
        int row = bm0 + (ty << 2) + ii;
        float4 r;
        r.x = acc[ii][0] + bv.x;
        r.y = acc[ii][1] + bv.y;
        r.z = acc[ii][2] + bv.z;
        r.w = acc[ii][3] + bv.w;
        if (resid) {
            float4 rv = *(const float4*)&resid[row*Nout + col];
            r.x += rv.x; r.y += rv.y; r.z += rv.z; r.w += rv.w;
        }
        if (relu) {
            r.x = fmaxf(r.x, 0.f); r.y = fmaxf(r.y, 0.f);
            r.z = fmaxf(r.z, 0.f); r.w = fmaxf(r.w, 0.f);
        }
        *(float4*)&C[row*Nout + col] = r;
    }
}

// ---------------- cell-binned windowed flash attention ----------------------
// grid: (NC2, B); 64 threads = 16 query slots x 4 heads.
// qkv layout: [M][384] (q | k | v). Output o: [M][128] in original token order.
#define SROW 132   // padded row stride (floats) to spread smem banks
__global__ void __launch_bounds__(64)
attn_kernel(const float* __restrict__ qkv, const float* __restrict__ pos,
            const float* __restrict__ sqv, float* __restrict__ o) {
    __shared__ float  Ks[32*SROW];
    __shared__ float  Vs[32*SROW];
    __shared__ float2 Ps[32];
    __shared__ float  Ss[32];
    __shared__ int    s_cs[12], s_ce[12];
    __shared__ int    s_nc;

    int b = blockIdx.y, cell = blockIdx.x;
    int cstart = g_cstart[b][cell];
    int ccount = g_cstart[b][cell+1] - cstart;
    if (ccount == 0) return;

    int tid  = threadIdx.x;
    int slot = tid & 15;
    int head = tid >> 4;

    // build merged candidate ranges: one contiguous ord-range per valid row
    if (tid == 0) {
        int cx = cell & (NCELL-1), cy = cell >> 4;
        int nc = 0;
        for (int dy = -5; dy <= 5; ++dy) {
            int yy = cy + dy;
            if (yy < 0 || yy >= NCELL) continue;
            int bb = abs(dy) > 1 ? abs(dy) - 1 : 0;
            int rem = 16 - bb*bb;
            if (rem < 0) continue;
            int kx = (int)floorf(sqrtf((float)rem)) + 1;
            int x0 = cx - kx; if (x0 < 0) x0 = 0;
            int x1 = cx + kx; if (x1 > NCELL-1) x1 = NCELL-1;
            int s = g_cstart[b][yy*NCELL + x0];
            int e = g_cstart[b][yy*NCELL + x1 + 1];
            if (e > s) { s_cs[nc] = s; s_ce[nc] = e; ++nc; }
        }
        s_nc = nc;
    }
    __syncthreads();
    int nc = s_nc;

    const float scale = 0.17677669529663687f;  // 1/sqrt(32)
    const float R2 = 0.0625f;
    const float NEG_INF = -CUDART_INF_F;

    for (int q0 = 0; q0 < ccount; q0 += 16) {
        bool active = (q0 + slot) < ccount;
        int qidx = active ? (q0 + slot) : 0;
        int qi = g_ord[b][cstart + qidx];
        int t = b*CN + qi;

        float4 qr[8];
        const float4* qp = (const float4*)&qkv[t*3*CD + head*CHD];
        #pragma unroll
        for (int u = 0; u < 8; ++u) {
            qr[u] = qp[u];
            qr[u].x *= scale; qr[u].y *= scale; qr[u].z *= scale; qr[u].w *= scale;
        }
        float2 pi  = ((const float2*)pos)[t];
        float  sqi = sqv[t];

        float m = -1e30f, l = 0.f;
        float4 acc[8];
        #pragma unroll
        for (int u = 0; u < 8; ++u) acc[u] = make_float4(0.f, 0.f, 0.f, 0.f);

        for (int ci = 0; ci < nc; ++ci) {
            int S = s_cs[ci], E = s_ce[ci];
            for (int j0 = S; j0 < E; j0 += 32) {
                __syncthreads();
                {
                    int r = tid >> 1, half = tid & 1;
                    int src = j0 + r;
                    // each thread loads 64 floats (16 float4) of the 128-float row
                    float4* kd = (float4*)&Ks[r*SROW] + half*16;
                    float4* vd = (float4*)&Vs[r*SROW] + half*16;
                    if (src < E) {
                        int tj = b*CN + g_ord[b][src];
                        const float4* kp = (const float4*)&qkv[tj*3*CD + CD]   + half*16;
                        const float4* vp = (const float4*)&qkv[tj*3*CD + 2*CD] + half*16;
                        #pragma unroll
                        for (int u = 0; u < 16; ++u) { kd[u] = kp[u]; vd[u] = vp[u]; }
                        if (half == 0) { Ps[r] = ((const float2*)pos)[tj]; Ss[r] = sqv[tj]; }
                    } else {
                        float4 z = make_float4(0.f,0.f,0.f,0.f);
                        #pragma unroll
                        for (int u = 0; u < 16; ++u) { kd[u] = z; vd[u] = z; }
                        if (half == 0) { Ps[r] = make_float2(0.f,0.f); Ss[r] = CUDART_INF_F; }
                    }
                }
                __syncthreads();

                for (int j = 0; j < 32; ++j) {
                    float2 pj = Ps[j];
                    float d2 = sqi + Ss[j] - 2.f*(pi.x*pj.x + pi.y*pj.y);
                    const float4* kr = (const float4*)&Ks[j*SROW + (head<<5)];
                    float sA = 0.f, sB = 0.f, sC = 0.f, sD = 0.f;
                    #pragma unroll
                    for (int u = 0; u < 8; ++u) {
                        float4 kk4 = kr[u];
                        sA = fmaf(qr[u].x, kk4.x, sA);
                        sB = fmaf(qr[u].y, kk4.y, sB);
                        sC = fmaf(qr[u].z, kk4.z, sC);
                        sD = fmaf(qr[u].w, kk4.w, sD);
                    }
                    float s = (d2 <= R2) ? ((sA + sB) + (sC + sD)) : NEG_INF;
                    if (s > m) {
                        float alpha = __expf(m - s);
                        m = s;
                        l *= alpha;
                        #pragma unroll
                        for (int u = 0; u < 8; ++u) {
                            acc[u].x *= alpha; acc[u].y *= alpha;
                            acc[u].z *= alpha; acc[u].w *= alpha;
                        }
                    }
                    float pb = __expf(s - m);
                    l += pb;
                    const float4* vr = (const float4*)&Vs[j*SROW + (head<<5)];
                    #pragma unroll
                    for (int u = 0; u < 8; ++u) {
                        float4 vv = vr[u];
                        acc[u].x = fmaf(pb, vv.x, acc[u].x);
                        acc[u].y = fmaf(pb, vv.y, acc[u].y);
                        acc[u].z = fmaf(pb, vv.z, acc[u].z);
                        acc[u].w = fmaf(pb, vv.w, acc[u].w);
                    }
                }
            }
        }

        if (active) {
            float inv = 1.f / l;
            float4* op = (float4*)&o[t*CD + head*CHD];
            #pragma unroll
            for (int u = 0; u < 8; ++u)
                op[u] = make_float4(acc[u].x*inv, acc[u].y*inv, acc[u].z*inv, acc[u].w*inv);
        }
    }
}

// ---------------- launch ----------------------------------------------------
extern "C" void kernel_launch(void* const* d_in, const int* in_sizes, int n_in,
                              void* d_out, int out_size) {
    const float* x    = (const float*)d_in[0];
    const float* pos  = (const float*)d_in[1];
    const float* Wq_w = (const float*)d_in[2];
    const float* Wq_b = (const float*)d_in[3];
    const float* Wk_w = (const float*)d_in[4];
    const float* Wk_b = (const float*)d_in[5];
    const float* Wv_w = (const float*)d_in[6];
    const float* Wv_b = (const float*)d_in[7];
    const float* Wo_w = (const float*)d_in[8];
    const float* Wo_b = (const float*)d_in[9];
    const float* n1_g = (const float*)d_in[10];
    const float* n1_b = (const float*)d_in[11];
    const float* n2_g = (const float*)d_in[12];
    const float* n2_b = (const float*)d_in[13];
    const float* l1_w = (const float*)d_in[14];
    const float* l1_b = (const float*)d_in[15];
    const float* l2_w = (const float*)d_in[16];
    const float* l2_b = (const float*)d_in[17];
    float* out = (float*)d_out;

    float *gx, *gxn, *gqkv, *go, *ghid, *gmu, *grstd, *gsq, *gwqkv, *gbqkv;
    double* gpart;
    cudaGetSymbolAddress((void**)&gx,    g_x);
    cudaGetSymbolAddress((void**)&gxn,   g_xn);
    cudaGetSymbolAddress((void**)&gqkv,  g_qkv);
    cudaGetSymbolAddress((void**)&go,    g_o);
    cudaGetSymbolAddress((void**)&ghid,  g_hid);
    cudaGetSymbolAddress((void**)&gpart, g_part);
    cudaGetSymbolAddress((void**)&gmu,   g_mu);
    cudaGetSymbolAddress((void**)&grstd, g_rstd);
    cudaGetSymbolAddress((void**)&gsq,   g_sq);
    cudaGetSymbolAddress((void**)&gwqkv, g_wqkv);
    cudaGetSymbolAddress((void**)&gbqkv, g_bqkv);

    copy_kernel<<<(CM*CD + 255)/256, 256>>>(x, gx, CM*CD);

    // spatial binning of positions (once; shared by both layers)
    zero_cnt_kernel<<<1, CB*NC2>>>();
    hist_kernel<<<(CM + 255)/256, 256>>>(pos);
    scan_kernel<<<1, 32>>>();
    scatter_kernel<<<(CM + 255)/256, 256>>>();

    dim3 gP(CM/64, CD/64);          // N=128 outputs
    dim3 gQKV(CM/64, 3*CD/64);      // N=384 fused qkv
    dim3 gF(CM/64, 2*CD/64);        // N=256 FFN hidden

    for (int i = 0; i < 2; ++i) {
        // --- attention block ---
        bn_stats_kernel<<<64, 128>>>(gx, gpart);
        bn_finalize_kernel<<<1, 128>>>(gpart, gmu, grstd);
        bn_apply_kernel<<<(CM*CD + 255)/256, 256>>>(gx, n1_g + i*CD, n1_b + i*CD, gmu, grstd, gxn);

        pack_qkv_kernel<<<(CD*3*CD + 255)/256, 256>>>(Wq_w + i*CD*CD, Wk_w + i*CD*CD, Wv_w + i*CD*CD,
                                                      Wq_b + i*CD, Wk_b + i*CD, Wv_b + i*CD);
        gemm_kernel<<<gQKV, 256>>>(gxn, gwqkv, gbqkv, nullptr, gqkv, CM, CD, 3*CD, 0);

        if (i == 0)
            rope_kernel<<<(CM*64 + 255)/256, 256>>>(gqkv, pos);

        attn_kernel<<<dim3(NC2, CB), 64>>>(gqkv, pos, gsq, go);

        gemm_kernel<<<gP, 256>>>(go, Wo_w + i*CD*CD, Wo_b + i*CD, gx, gx, CM, CD, CD, 0);

        // --- FFN block ---
        bn_stats_kernel<<<64, 128>>>(gx, gpart);
        bn_finalize_kernel<<<1, 128>>>(gpart, gmu, grstd);
        bn_apply_kernel<<<(CM*CD + 255)/256, 256>>>(gx, n2_g + i*CD, n2_b + i*CD, gmu, grstd, gxn);

        gemm_kernel<<<gF, 256>>>(gxn, l1_w + i*CD*2*CD, l1_b + i*2*CD, nullptr, ghid, CM, CD, 2*CD, 1);

        float* dst = (i == 1) ? out : gx;
        gemm_kernel<<<gP, 256>>>(ghid, l2_w + i*2*CD*CD, l2_b + i*CD, gx, dst, CM, 2*CD, CD, 0);
    }
}

// round 4
// speedup vs baseline: 2.0807x; 1.7704x over previous
#include <cuda_runtime.h>
#include <math_constants.h>

#define CB 2
#define CN 4096
#define CD 128
#define CH 4
#define CHD 32
#define CM (CB*CN)   // 8192 tokens
#define NCELL 16
#define NC2 (NCELL*NCELL)
#define CAND_CAP 2048

typedef unsigned long long ull;

// ---------------- f32x2 packed helpers (sm_100+ PTX) -----------------------
__device__ __forceinline__ ull ffma2(ull a, ull b, ull c) {
    ull d; asm("fma.rn.f32x2 %0,%1,%2,%3;" : "=l"(d) : "l"(a), "l"(b), "l"(c)); return d;
}
__device__ __forceinline__ ull fmul2(ull a, ull b) {
    ull d; asm("mul.rn.f32x2 %0,%1,%2;" : "=l"(d) : "l"(a), "l"(b)); return d;
}
__device__ __forceinline__ ull fadd2(ull a, ull b) {
    ull d; asm("add.rn.f32x2 %0,%1,%2;" : "=l"(d) : "l"(a), "l"(b)); return d;
}
__device__ __forceinline__ ull fpack2(float lo, float hi) {
    ull d; asm("mov.b64 %0,{%1,%2};" : "=l"(d) : "f"(lo), "f"(hi)); return d;
}
__device__ __forceinline__ void funpack2(ull a, float& lo, float& hi) {
    asm("mov.b64 {%0,%1},%2;" : "=f"(lo), "=f"(hi) : "l"(a));
}

// ---------------- scratch ---------------------------------------------------
__device__ float  g_x   [CM*CD];
__device__ float  g_xn  [CM*CD];
__device__ float  g_qkv [CM*3*CD];
__device__ float  g_o   [CM*CD];
__device__ float  g_hid [CM*2*CD];
__device__ double g_part[64*2*CD];
__device__ float  g_mu  [CD];
__device__ float  g_rstd[CD];
__device__ float  g_sq  [CM];
__device__ float  g_wqkv[CD*3*CD];
__device__ float  g_bqkv[3*CD];
// spatial binning + candidate lists
__device__ int g_cnt   [CB][NC2];
__device__ int g_cstart[CB][NC2+1];
__device__ int g_cursor[CB][NC2];
__device__ int g_ord   [CB][CN];
__device__ int g_cellid[CB][CN];
__device__ int g_cand  [CB*NC2*CAND_CAP];
__device__ int g_ncand [CB*NC2];
// attention partials: [half][token][head]
__device__ float g_pm  [2*CM*CH];
__device__ float g_pl  [2*CM*CH];
__device__ float g_pacc[2*CM*CH*32];

// ---------------- small utility kernels ------------------------------------
__global__ void copy_kernel(const float* __restrict__ src, float* __restrict__ dst, int n) {
    int i = blockIdx.x * blockDim.x + threadIdx.x;
    if (i < n) dst[i] = src[i];
}

__global__ void zero_cnt_kernel() {
    int i = threadIdx.x;
    if (i < CB*NC2) ((int*)g_cnt)[i] = 0;
}

__global__ void hist_kernel(const float* __restrict__ pos) {
    int t = blockIdx.x * blockDim.x + threadIdx.x;
    if (t >= CM) return;
    int b = t >> 12, n = t & (CN-1);
    float px = pos[2*t], py = pos[2*t+1];
    int cx = min(NCELL-1, max(0, (int)(px * NCELL)));
    int cy = min(NCELL-1, max(0, (int)(py * NCELL)));
    int c = cy*NCELL + cx;
    g_cellid[b][n] = c;
    atomicAdd(&g_cnt[b][c], 1);
    g_sq[t] = px*px + py*py;
}

// parallel per-batch exclusive scan over 256 cells
__global__ void scan_kernel() {
    __shared__ int sm[NC2];
    int b = blockIdx.x;
    int c = threadIdx.x;
    int v = g_cnt[b][c];
    sm[c] = v;
    __syncthreads();
    for (int off = 1; off < NC2; off <<= 1) {
        int t = (c >= off) ? sm[c-off] : 0;
        __syncthreads();
        if (c >= off) sm[c] += t;
        __syncthreads();
    }
    int excl = sm[c] - v;
    g_cstart[b][c] = excl;
    g_cursor[b][c] = excl;
    if (c == NC2-1) g_cstart[b][NC2] = sm[c];
}

__global__ void scatter_kernel() {
    int t = blockIdx.x * blockDim.x + threadIdx.x;
    if (t >= CM) return;
    int b = t >> 12, n = t & (CN-1);
    int c = g_cellid[b][n];
    int r = atomicAdd(&g_cursor[b][c], 1);
    g_ord[b][r] = n;
}

// ---------------- candidate list build: one warp per (b,cell) ---------------
__global__ void __launch_bounds__(128)
build_cands_kernel(const float* __restrict__ pos) {
    int wid = threadIdx.x >> 5, lane = threadIdx.x & 31;
    int cidx = blockIdx.x * 4 + wid;          // 0 .. CB*NC2-1
    int b = cidx >> 8, cell = cidx & (NC2-1);
    int cx = cell & (NCELL-1), cy = cell >> 4;
    float X0 = cx * (1.f/NCELL), X1 = (cx+1) * (1.f/NCELL);
    float Y0 = cy * (1.f/NCELL), Y1 = (cy+1) * (1.f/NCELL);
    const float R2m = 0.0625f + 1e-4f;        // small safety margin (superset)
    int* dst = &g_cand[cidx * CAND_CAP];
    int cnt = 0;
    for (int dy = -5; dy <= 5; ++dy) {
        int yy = cy + dy;
        if (yy < 0 || yy >= NCELL) continue;
        int bb = abs(dy) > 1 ? abs(dy) - 1 : 0;
        int rem = 16 - bb*bb;
        if (rem < 0) continue;
        int kx = (int)floorf(sqrtf((float)rem)) + 1;
        int x0 = cx - kx; if (x0 < 0) x0 = 0;
        int x1 = cx + kx; if (x1 > NCELL-1) x1 = NCELL-1;
        int S = g_cstart[b][yy*NCELL + x0];
        int E = g_cstart[b][yy*NCELL + x1 + 1];
        for (int j0 = S; j0 < E; j0 += 32) {
            int src = j0 + lane;
            bool keep = false; int tok = 0;
            if (src < E) {
                tok = g_ord[b][src];
                float2 p = ((const float2*)pos)[b*CN + tok];
                float ddx = fmaxf(fmaxf(X0 - p.x, p.x - X1), 0.f);
                float ddy = fmaxf(fmaxf(Y0 - p.y, p.y - Y1), 0.f);
                keep = (ddx*ddx + ddy*ddy) <= R2m;
            }
            unsigned bal = __ballot_sync(0xFFFFFFFFu, keep);
            int ofs = __popc(bal & ((1u << lane) - 1));
            if (keep && cnt + ofs < CAND_CAP) dst[cnt + ofs] = tok;
            cnt += __popc(bal);
        }
    }
    if (cnt > CAND_CAP) cnt = CAND_CAP;
    if (lane == 0) g_ncand[cidx] = cnt;
}

// ---------------- BatchNorm -------------------------------------------------
__global__ void bn_stats_kernel(const float* __restrict__ x, double* __restrict__ part) {
    int d = threadIdx.x;
    int blk = blockIdx.x;
    int r0 = blk * (CM / 64);
    double s = 0.0, s2 = 0.0;
    for (int r = 0; r < CM/64; ++r) {
        float v = x[(r0 + r)*CD + d];
        s  += (double)v;
        s2 += (double)v * (double)v;
    }
    part[blk*2*CD + d]      = s;
    part[blk*2*CD + CD + d] = s2;
}

__global__ void bn_finalize_kernel(const double* __restrict__ part,
                                   float* __restrict__ mu, float* __restrict__ rstd) {
    int d = threadIdx.x;
    double s0=0, s1=0, s2=0, s3=0, q0=0, q1=0, q2=0, q3=0;
    #pragma unroll
    for (int b = 0; b < 64; b += 4) {
        s0 += part[(b+0)*2*CD + d];      q0 += part[(b+0)*2*CD + CD + d];
        s1 += part[(b+1)*2*CD + d];      q1 += part[(b+1)*2*CD + CD + d];
        s2 += part[(b+2)*2*CD + d];      q2 += part[(b+2)*2*CD + CD + d];
        s3 += part[(b+3)*2*CD + d];      q3 += part[(b+3)*2*CD + CD + d];
    }
    double s = (s0+s1)+(s2+s3);
    double sq = (q0+q1)+(q2+q3);
    double m   = s / (double)CM;
    double var = sq / (double)CM - m*m;
    mu[d]   = (float)m;
    rstd[d] = rsqrtf((float)var + 1e-5f);
}

__global__ void bn_apply_kernel(const float* __restrict__ x,
                                const float* __restrict__ g, const float* __restrict__ b,
                                const float* __restrict__ mu, const float* __restrict__ rstd,
                                float* __restrict__ y) {
    int i = blockIdx.x * blockDim.x + threadIdx.x;
    if (i < CM*CD) {
        int d = i & (CD - 1);
        y[i] = (x[i] - mu[d]) * rstd[d] * g[d] + b[d];
    }
}

// ---------------- pack QKV weights ------------------------------------------
__global__ void pack_qkv_kernel(const float* __restrict__ Wq, const float* __restrict__ Wk,
                                const float* __restrict__ Wv,
                                const float* __restrict__ bq, const float* __restrict__ bk,
                                const float* __restrict__ bv) {
    int t = blockIdx.x * blockDim.x + threadIdx.x;
    if (t < CD*3*CD) {
        int row = t / (3*CD), col = t % (3*CD);
        int sel = col >> 7, c = col & (CD-1);
        const float* W = (sel == 0) ? Wq : (sel == 1) ? Wk : Wv;
        g_wqkv[t] = W[row*CD + c];
    }
    if (t < 3*CD) {
        int sel = t >> 7, c = t & (CD-1);
        const float* bb = (sel == 0) ? bq : (sel == 1) ? bk : bv;
        g_bqkv[t] = bb[c];
    }
}

// ---------------- RoPE (layer 0 only) ---------------------------------------
__global__ void rope_kernel(float* __restrict__ qkv, const float* __restrict__ pos) {
    int idx = blockIdx.x * blockDim.x + threadIdx.x;
    if (idx >= CM * 64) return;
    int p = idx & 63;
    int t = idx >> 6;
    int group = p >> 5;
    int fidx  = p & 31;
    float freq = 3.14159265358979324f * (float)(fidx + 1);
    float ang = pos[t*2 + group] * freq;
    float sv, cv;
    sincosf(ang, &sv, &cv);
    int qb = t*3*CD + (p << 1);
    float q0 = qkv[qb], q1 = qkv[qb+1];
    qkv[qb]   = cv*q0 - sv*q1;
    qkv[qb+1] = cv*q1 + sv*q0;
    int kb = qb + CD;
    float k0 = qkv[kb], k1 = qkv[kb+1];
    qkv[kb]   = cv*k0 - sv*k1;
    qkv[kb+1] = cv*k1 + sv*k0;
}

// ---------------- SGEMM -----------------------------------------------------
__global__ void __launch_bounds__(256)
gemm_kernel(const float* __restrict__ A, const float* __restrict__ W,
            const float* __restrict__ bias, const float* __restrict__ resid,
            float* __restrict__ C, int M, int K, int Nout, int relu) {
    __shared__ float As[16][64];
    __shared__ float Ws[16][64];
    int tid = threadIdx.x;
    int tx = tid & 15, ty = tid >> 4;
    int bm0 = blockIdx.x * 64, bn0 = blockIdx.y * 64;

    float acc[4][4] = {};

    int ar  = tid >> 2;
    int acq = (tid & 3) << 2;
    int wr  = tid >> 4;
    int wc  = (tid & 15) << 2;

    for (int k0 = 0; k0 < K; k0 += 16) {
        float4 av = *(const float4*)&A[(bm0 + ar)*K + k0 + acq];
        float4 wv = *(const float4*)&W[(k0 + wr)*Nout + bn0 + wc];
        __syncthreads();
        As[acq+0][ar] = av.x;
        As[acq+1][ar] = av.y;
        As[acq+2][ar] = av.z;
        As[acq+3][ar] = av.w;
        *(float4*)&Ws[wr][wc] = wv;
        __syncthreads();
        #pragma unroll
        for (int kk = 0; kk < 16; ++kk) {
            float4 a  = *(const float4*)&As[kk][ty << 2];
            float4 b4 = *(const float4*)&Ws[kk][tx << 2];
            float avv[4] = {a.x, a.y, a.z, a.w};
            float bvv[4] = {b4.x, b4.y, b4.z, b4.w};
            #pragma unroll
            for (int ii = 0; ii < 4; ++ii)
                #pragma unroll
                for (int jj = 0; jj < 4; ++jj)
                    acc[ii][jj] = fmaf(avv[ii], bvv[jj], acc[ii][jj]);
        }
    }

    int col = bn0 + (tx << 2);
    float4 bv = *(const float4*)&bias[col];
    #pragma unroll
    for (int ii = 0; ii < 4; ++ii) {
        int row = bm0 + (ty << 2) + ii;
        float4 r;
        r.x = acc[ii][0] + bv.x;
        r.y = acc[ii][1] + bv.y;
        r.z = acc[ii][2] + bv.z;
        r.w = acc[ii][3] + bv.w;
        if (resid) {
            float4 rv = *(const float4*)&resid[row*Nout + col];
            r.x += rv.x; r.y += rv.y; r.z += rv.z; r.w += rv.w;
        }
        if (relu) {
            r.x = fmaxf(r.x, 0.f); r.y = fmaxf(r.y, 0.f);
            r.z = fmaxf(r.z, 0.f); r.w = fmaxf(r.w, 0.f);
        }
        *(float4*)&C[row*Nout + col] = r;
    }
}

// ---------------- attention: candidate-list flash with f32x2 + j-split ------
// grid (NC2, 4 qtiles, CB*2 jhalf); 64 threads = 16 slots x 4 heads.
#define SROW 132
__global__ void __launch_bounds__(64)
attn_kernel(const float* __restrict__ qkv, const float* __restrict__ pos,
            const float* __restrict__ sqv) {
    __shared__ float  Ks[32*SROW];
    __shared__ float  Vs[32*SROW];
    __shared__ float2 Ps[32];
    __shared__ float  Ss[32];

    int cell = blockIdx.x, qt = blockIdx.y;
    int b = blockIdx.z >> 1, jh = blockIdx.z & 1;
    int cidx = b*NC2 + cell;
    int cstart = g_cstart[b][cell];
    int ccount = g_cstart[b][cell+1] - cstart;
    if (qt*16 >= ccount) return;

    int ncand = g_ncand[cidx];
    const int* cand = &g_cand[cidx*CAND_CAP];
    int half0 = ncand >> 1;
    int jstart = jh ? half0 : 0;
    int jend   = jh ? ncand : half0;

    int tid  = threadIdx.x;
    int slot = tid & 15;
    int head = tid >> 4;

    const float scale = 0.17677669529663687f;  // 1/sqrt(32)
    const float R2 = 0.0625f;
    const float NEG_INF = -CUDART_INF_F;
    ull scale2 = fpack2(scale, scale);

    for (int q0 = qt*16; q0 < ccount; q0 += 64) {
        bool active = (q0 + slot) < ccount;
        int qidx = active ? (q0 + slot) : 0;
        int qi = g_ord[b][cstart + qidx];
        int t = b*CN + qi;

        ull qr2[16];
        const ulonglong2* qp = (const ulonglong2*)&qkv[t*3*CD + head*CHD];
        #pragma unroll
        for (int u = 0; u < 8; ++u) {
            ulonglong2 qq = qp[u];
            qr2[2*u]   = fmul2(qq.x, scale2);
            qr2[2*u+1] = fmul2(qq.y, scale2);
        }
        float2 pi  = ((const float2*)pos)[t];
        float  sqi = sqv[t];

        float m = -1e30f, l = 0.f;
        ull acc2[16];
        #pragma unroll
        for (int u = 0; u < 16; ++u) acc2[u] = 0ull;

        for (int j0 = jstart; j0 < jend; j0 += 32) {
            __syncthreads();
            {
                int r = tid >> 1, half = tid & 1;
                int src = j0 + r;
                float4* kd = (float4*)&Ks[r*SROW] + half*16;
                float4* vd = (float4*)&Vs[r*SROW] + half*16;
                if (src < jend) {
                    int tj = b*CN + cand[src];
                    const float4* kp = (const float4*)&qkv[tj*3*CD + CD]   + half*16;
                    const float4* vp = (const float4*)&qkv[tj*3*CD + 2*CD] + half*16;
                    #pragma unroll
                    for (int u = 0; u < 16; ++u) { kd[u] = kp[u]; vd[u] = vp[u]; }
                    if (half == 0) { Ps[r] = ((const float2*)pos)[tj]; Ss[r] = sqv[tj]; }
                } else {
                    float4 z = make_float4(0.f,0.f,0.f,0.f);
                    #pragma unroll
                    for (int u = 0; u < 16; ++u) { kd[u] = z; vd[u] = z; }
                    if (half == 0) { Ps[r] = make_float2(0.f,0.f); Ss[r] = CUDART_INF_F; }
                }
            }
            __syncthreads();

            for (int j = 0; j < 32; ++j) {
                float2 pj = Ps[j];
                float d2 = sqi + Ss[j] - 2.f*(pi.x*pj.x + pi.y*pj.y);
                bool inw = (d2 <= R2);
                if (__ballot_sync(0xFFFFFFFFu, inw) == 0u) continue;

                const ulonglong2* kr = (const ulonglong2*)&Ks[j*SROW + (head<<5)];
                ull sa = 0ull, sb = 0ull;
                #pragma unroll
                for (int u = 0; u < 4; ++u) {
                    ulonglong2 k0v = kr[2*u], k1v = kr[2*u+1];
                    sa = ffma2(qr2[4*u],   k0v.x, sa);
                    sb = ffma2(qr2[4*u+1], k0v.y, sb);
                    sa = ffma2(qr2[4*u+2], k1v.x, sa);
                    sb = ffma2(qr2[4*u+3], k1v.y, sb);
                }
                float sl, sh, s;
                funpack2(fadd2(sa, sb), sl, sh);
                s = inw ? (sl + sh) : NEG_INF;

                if (s > m) {
                    float alpha = __expf(m - s);
                    m = s;
                    l *= alpha;
                    ull alpha2 = fpack2(alpha, alpha);
                    #pragma unroll
                    for (int u = 0; u < 16; ++u) acc2[u] = fmul2(acc2[u], alpha2);
                }
                float pb = __expf(s - m);
                l += pb;
                ull pb2 = fpack2(pb, pb);
                const ulonglong2* vr = (const ulonglong2*)&Vs[j*SROW + (head<<5)];
                #pragma unroll
                for (int u = 0; u < 8; ++u) {
                    ulonglong2 vv = vr[u];
                    acc2[2*u]   = ffma2(pb2, vv.x, acc2[2*u]);
                    acc2[2*u+1] = ffma2(pb2, vv.y, acc2[2*u+1]);
                }
            }
        }

        if (active) {
            int pidx = (jh*CM + t)*CH + head;
            g_pm[pidx] = m;
            g_pl[pidx] = l;
            ulonglong2* ap = (ulonglong2*)&g_pacc[pidx*32];
            #pragma unroll
            for (int u = 0; u < 8; ++u) {
                ulonglong2 w; w.x = acc2[2*u]; w.y = acc2[2*u+1];
                ap[u] = w;
            }
        }
    }
}

// ---------------- merge two attention halves, normalize, write o -----------
__global__ void merge_kernel(float* __restrict__ o) {
    int idx = blockIdx.x * blockDim.x + threadIdx.x;   // CM*CH*4
    if (idx >= CM*CH*4) return;
    int q8 = idx & 3;
    int h  = (idx >> 2) & 3;
    int t  = idx >> 4;
    int i0 = t*CH + h;
    int i1 = (CM + t)*CH + h;
    float m0 = g_pm[i0], m1 = g_pm[i1];
    float l0 = g_pl[i0], l1 = g_pl[i1];
    float m = fmaxf(m0, m1);
    float f0 = __expf(m0 - m), f1 = __expf(m1 - m);
    float inv = 1.f / (l0*f0 + l1*f1);
    f0 *= inv; f1 *= inv;
    const float4* a0 = (const float4*)&g_pacc[i0*32 + q8*8];
    const float4* a1 = (const float4*)&g_pacc[i1*32 + q8*8];
    float4* op = (float4*)&o[t*CD + h*CHD + q8*8];
    #pragma unroll
    for (int u = 0; u < 2; ++u) {
        float4 x0 = a0[u], x1 = a1[u];
        float4 r;
        r.x = x0.x*f0 + x1.x*f1;
        r.y = x0.y*f0 + x1.y*f1;
        r.z = x0.z*f0 + x1.z*f1;
        r.w = x0.w*f0 + x1.w*f1;
        op[u] = r;
    }
}

// ---------------- launch ----------------------------------------------------
extern "C" void kernel_launch(void* const* d_in, const int* in_sizes, int n_in,
                              void* d_out, int out_size) {
    const float* x    = (const float*)d_in[0];
    const float* pos  = (const float*)d_in[1];
    const float* Wq_w = (const float*)d_in[2];
    const float* Wq_b = (const float*)d_in[3];
    const float* Wk_w = (const float*)d_in[4];
    const float* Wk_b = (const float*)d_in[5];
    const float* Wv_w = (const float*)d_in[6];
    const float* Wv_b = (const float*)d_in[7];
    const float* Wo_w = (const float*)d_in[8];
    const float* Wo_b = (const float*)d_in[9];
    const float* n1_g = (const float*)d_in[10];
    const float* n1_b = (const float*)d_in[11];
    const float* n2_g = (const float*)d_in[12];
    const float* n2_b = (const float*)d_in[13];
    const float* l1_w = (const float*)d_in[14];
    const float* l1_b = (const float*)d_in[15];
    const float* l2_w = (const float*)d_in[16];
    const float* l2_b = (const float*)d_in[17];
    float* out = (float*)d_out;

    float *gx, *gxn, *gqkv, *go, *ghid, *gmu, *grstd, *gsq, *gwqkv, *gbqkv;
    double* gpart;
    cudaGetSymbolAddress((void**)&gx,    g_x);
    cudaGetSymbolAddress((void**)&gxn,   g_xn);
    cudaGetSymbolAddress((void**)&gqkv,  g_qkv);
    cudaGetSymbolAddress((void**)&go,    g_o);
    cudaGetSymbolAddress((void**)&ghid,  g_hid);
    cudaGetSymbolAddress((void**)&gpart, g_part);
    cudaGetSymbolAddress((void**)&gmu,   g_mu);
    cudaGetSymbolAddress((void**)&grstd, g_rstd);
    cudaGetSymbolAddress((void**)&gsq,   g_sq);
    cudaGetSymbolAddress((void**)&gwqkv, g_wqkv);
    cudaGetSymbolAddress((void**)&gbqkv, g_bqkv);

    copy_kernel<<<(CM*CD + 255)/256, 256>>>(x, gx, CM*CD);

    // spatial binning + per-cell candidate lists (once; shared by both layers)
    zero_cnt_kernel<<<1, CB*NC2>>>();
    hist_kernel<<<(CM + 255)/256, 256>>>(pos);
    scan_kernel<<<CB, NC2>>>();
    scatter_kernel<<<(CM + 255)/256, 256>>>();
    build_cands_kernel<<<CB*NC2/4, 128>>>(pos);

    dim3 gP(CM/64, CD/64);
    dim3 gQKV(CM/64, 3*CD/64);
    dim3 gF(CM/64, 2*CD/64);

    for (int i = 0; i < 2; ++i) {
        // --- attention block ---
        bn_stats_kernel<<<64, 128>>>(gx, gpart);
        bn_finalize_kernel<<<1, 128>>>(gpart, gmu, grstd);
        bn_apply_kernel<<<(CM*CD + 255)/256, 256>>>(gx, n1_g + i*CD, n1_b + i*CD, gmu, grstd, gxn);

        pack_qkv_kernel<<<(CD*3*CD + 255)/256, 256>>>(Wq_w + i*CD*CD, Wk_w + i*CD*CD, Wv_w + i*CD*CD,
                                                      Wq_b + i*CD, Wk_b + i*CD, Wv_b + i*CD);
        gemm_kernel<<<gQKV, 256>>>(gxn, gwqkv, gbqkv, nullptr, gqkv, CM, CD, 3*CD, 0);

        if (i == 0)
            rope_kernel<<<(CM*64 + 255)/256, 256>>>(gqkv, pos);

        attn_kernel<<<dim3(NC2, 4, CB*2), 64>>>(gqkv, pos, gsq);
        merge_kernel<<<(CM*CH*4 + 255)/256, 256>>>(go);

        gemm_kernel<<<gP, 256>>>(go, Wo_w + i*CD*CD, Wo_b + i*CD, gx, gx, CM, CD, CD, 0);

        // --- FFN block ---
        bn_stats_kernel<<<64, 128>>>(gx, gpart);
        bn_finalize_kernel<<<1, 128>>>(gpart, gmu, grstd);
        bn_apply_kernel<<<(CM*CD + 255)/256, 256>>>(gx, n2_g + i*CD, n2_b + i*CD, gmu, grstd, gxn);

        gemm_kernel<<<gF, 256>>>(gxn, l1_w + i*CD*2*CD, l1_b + i*2*CD, nullptr, ghid, CM, CD, 2*CD, 1);

        float* dst = (i == 1) ? out : gx;
        gemm_kernel<<<gP, 256>>>(ghid, l2_w + i*2*CD*CD, l2_b + i*CD, gx, dst, CM, 2*CD, CD, 0);
    }
}

// round 5
// speedup vs baseline: 2.1799x; 1.0477x over previous
#include <cuda_runtime.h>
#include <math_constants.h>

#define CB 2
#define CN 4096
#define CD 128
#define CH 4
#define CHD 32
#define CM (CB*CN)   // 8192 tokens
#define NCELL 16
#define NC2 (NCELL*NCELL)
#define CAND_CAP 2048

typedef unsigned long long ull;

// ---------------- f32x2 packed helpers (sm_100+ PTX) -----------------------
__device__ __forceinline__ ull ffma2(ull a, ull b, ull c) {
    ull d; asm("fma.rn.f32x2 %0,%1,%2,%3;" : "=l"(d) : "l"(a), "l"(b), "l"(c)); return d;
}
__device__ __forceinline__ ull fmul2(ull a, ull b) {
    ull d; asm("mul.rn.f32x2 %0,%1,%2;" : "=l"(d) : "l"(a), "l"(b)); return d;
}
__device__ __forceinline__ ull fadd2(ull a, ull b) {
    ull d; asm("add.rn.f32x2 %0,%1,%2;" : "=l"(d) : "l"(a), "l"(b)); return d;
}
__device__ __forceinline__ ull fpack2(float lo, float hi) {
    ull d; asm("mov.b64 %0,{%1,%2};" : "=l"(d) : "f"(lo), "f"(hi)); return d;
}
__device__ __forceinline__ void funpack2(ull a, float& lo, float& hi) {
    asm("mov.b64 {%0,%1},%2;" : "=f"(lo), "=f"(hi) : "l"(a));
}

// ---------------- tf32 split helpers ----------------------------------------
__device__ __forceinline__ void tf32split(float x, float& hi, float& lo) {
    unsigned h;
    asm("cvt.rna.tf32.f32 %0, %1;" : "=r"(h) : "f"(x));
    float hf = __uint_as_float(h);
    float l = x - hf;
    unsigned lb;
    asm("cvt.rna.tf32.f32 %0, %1;" : "=r"(lb) : "f"(l));
    hi = hf; lo = __uint_as_float(lb);
}

__device__ __forceinline__ void mma_tf32(float* c, const unsigned* a, const unsigned* b) {
    asm volatile(
        "mma.sync.aligned.m16n8k8.row.col.f32.tf32.tf32.f32 "
        "{%0,%1,%2,%3},{%4,%5,%6,%7},{%8,%9},{%0,%1,%2,%3};\n"
        : "+f"(c[0]), "+f"(c[1]), "+f"(c[2]), "+f"(c[3])
        : "r"(a[0]), "r"(a[1]), "r"(a[2]), "r"(a[3]), "r"(b[0]), "r"(b[1]));
}

// ---------------- scratch ---------------------------------------------------
__device__ float  g_x   [CM*CD];
__device__ float  g_xn  [CM*CD];
__device__ float  g_qkv [CM*3*CD];
__device__ float  g_o   [CM*CD];
__device__ float  g_hid [CM*2*CD];
__device__ double g_part[64*2*CD];
__device__ float  g_mu  [CD];
__device__ float  g_rstd[CD];
__device__ float  g_sq  [CM];
__device__ float  g_wqkv[CD*3*CD];
__device__ float  g_bqkv[3*CD];
// spatial binning + candidate lists
__device__ int g_cnt   [CB][NC2];
__device__ int g_cstart[CB][NC2+1];
__device__ int g_cursor[CB][NC2];
__device__ int g_ord   [CB][CN];
__device__ int g_cellid[CB][CN];
__device__ int g_cand  [CB*NC2*CAND_CAP];
__device__ int g_ncand [CB*NC2];
// attention partials: [half][token][head]
__device__ float g_pm  [2*CM*CH];
__device__ float g_pl  [2*CM*CH];
__device__ float g_pacc[2*CM*CH*32];

// ---------------- small utility kernels ------------------------------------
__global__ void copy_kernel(const float* __restrict__ src, float* __restrict__ dst, int n) {
    int i = blockIdx.x * blockDim.x + threadIdx.x;
    if (i < n) dst[i] = src[i];
}

__global__ void zero_cnt_kernel() {
    int i = threadIdx.x;
    if (i < CB*NC2) ((int*)g_cnt)[i] = 0;
}

__global__ void hist_kernel(const float* __restrict__ pos) {
    int t = blockIdx.x * blockDim.x + threadIdx.x;
    if (t >= CM) return;
    int b = t >> 12, n = t & (CN-1);
    float px = pos[2*t], py = pos[2*t+1];
    int cx = min(NCELL-1, max(0, (int)(px * NCELL)));
    int cy = min(NCELL-1, max(0, (int)(py * NCELL)));
    int c = cy*NCELL + cx;
    g_cellid[b][n] = c;
    atomicAdd(&g_cnt[b][c], 1);
    g_sq[t] = px*px + py*py;
}

// parallel per-batch exclusive scan over 256 cells
__global__ void scan_kernel() {
    __shared__ int sm[NC2];
    int b = blockIdx.x;
    int c = threadIdx.x;
    int v = g_cnt[b][c];
    sm[c] = v;
    __syncthreads();
    for (int off = 1; off < NC2; off <<= 1) {
        int t = (c >= off) ? sm[c-off] : 0;
        __syncthreads();
        if (c >= off) sm[c] += t;
        __syncthreads();
    }
    int excl = sm[c] - v;
    g_cstart[b][c] = excl;
    g_cursor[b][c] = excl;
    if (c == NC2-1) g_cstart[b][NC2] = sm[c];
}

__global__ void scatter_kernel() {
    int t = blockIdx.x * blockDim.x + threadIdx.x;
    if (t >= CM) return;
    int b = t >> 12, n = t & (CN-1);
    int c = g_cellid[b][n];
    int r = atomicAdd(&g_cursor[b][c], 1);
    g_ord[b][r] = n;
}

// ---------------- candidate list build: one warp per (b,cell) ---------------
__global__ void __launch_bounds__(128)
build_cands_kernel(const float* __restrict__ pos) {
    int wid = threadIdx.x >> 5, lane = threadIdx.x & 31;
    int cidx = blockIdx.x * 4 + wid;          // 0 .. CB*NC2-1
    int b = cidx >> 8, cell = cidx & (NC2-1);
    int cx = cell & (NCELL-1), cy = cell >> 4;
    float X0 = cx * (1.f/NCELL), X1 = (cx+1) * (1.f/NCELL);
    float Y0 = cy * (1.f/NCELL), Y1 = (cy+1) * (1.f/NCELL);
    const float R2m = 0.0625f + 1e-4f;        // small safety margin (superset)
    int* dst = &g_cand[cidx * CAND_CAP];
    int cnt = 0;
    for (int dy = -5; dy <= 5; ++dy) {
        int yy = cy + dy;
        if (yy < 0 || yy >= NCELL) continue;
        int bb = abs(dy) > 1 ? abs(dy) - 1 : 0;
        int rem = 16 - bb*bb;
        if (rem < 0) continue;
        int kx = (int)floorf(sqrtf((float)rem)) + 1;
        int x0 = cx - kx; if (x0 < 0) x0 = 0;
        int x1 = cx + kx; if (x1 > NCELL-1) x1 = NCELL-1;
        int S = g_cstart[b][yy*NCELL + x0];
        int E = g_cstart[b][yy*NCELL + x1 + 1];
        for (int j0 = S; j0 < E; j0 += 32) {
            int src = j0 + lane;
            bool keep = false; int tok = 0;
            if (src < E) {
                tok = g_ord[b][src];
                float2 p = ((const float2*)pos)[b*CN + tok];
                float ddx = fmaxf(fmaxf(X0 - p.x, p.x - X1), 0.f);
                float ddy = fmaxf(fmaxf(Y0 - p.y, p.y - Y1), 0.f);
                keep = (ddx*ddx + ddy*ddy) <= R2m;
            }
            unsigned bal = __ballot_sync(0xFFFFFFFFu, keep);
            int ofs = __popc(bal & ((1u << lane) - 1));
            if (keep && cnt + ofs < CAND_CAP) dst[cnt + ofs] = tok;
            cnt += __popc(bal);
        }
    }
    if (cnt > CAND_CAP) cnt = CAND_CAP;
    if (lane == 0) g_ncand[cidx] = cnt;
}

// ---------------- BatchNorm -------------------------------------------------
__global__ void bn_stats_kernel(const float* __restrict__ x, double* __restrict__ part) {
    int d = threadIdx.x;
    int blk = blockIdx.x;
    int r0 = blk * (CM / 64);
    double s = 0.0, s2 = 0.0;
    for (int r = 0; r < CM/64; ++r) {
        float v = x[(r0 + r)*CD + d];
        s  += (double)v;
        s2 += (double)v * (double)v;
    }
    part[blk*2*CD + d]      = s;
    part[blk*2*CD + CD + d] = s2;
}

__global__ void bn_finalize_kernel(const double* __restrict__ part,
                                   float* __restrict__ mu, float* __restrict__ rstd) {
    int d = threadIdx.x;
    double s0=0, s1=0, s2=0, s3=0, q0=0, q1=0, q2=0, q3=0;
    #pragma unroll
    for (int b = 0; b < 64; b += 4) {
        s0 += part[(b+0)*2*CD + d];      q0 += part[(b+0)*2*CD + CD + d];
        s1 += part[(b+1)*2*CD + d];      q1 += part[(b+1)*2*CD + CD + d];
        s2 += part[(b+2)*2*CD + d];      q2 += part[(b+2)*2*CD + CD + d];
        s3 += part[(b+3)*2*CD + d];      q3 += part[(b+3)*2*CD + CD + d];
    }
    double s = (s0+s1)+(s2+s3);
    double sq = (q0+q1)+(q2+q3);
    double m   = s / (double)CM;
    double var = sq / (double)CM - m*m;
    mu[d]   = (float)m;
    rstd[d] = rsqrtf((float)var + 1e-5f);
}

__global__ void bn_apply_kernel(const float* __restrict__ x,
                                const float* __restrict__ g, const float* __restrict__ b,
                                const float* __restrict__ mu, const float* __restrict__ rstd,
                                float* __restrict__ y) {
    int i = blockIdx.x * blockDim.x + threadIdx.x;
    if (i < CM*CD) {
        int d = i & (CD - 1);
        y[i] = (x[i] - mu[d]) * rstd[d] * g[d] + b[d];
    }
}

// ---------------- pack QKV weights ------------------------------------------
__global__ void pack_qkv_kernel(const float* __restrict__ Wq, const float* __restrict__ Wk,
                                const float* __restrict__ Wv,
                                const float* __restrict__ bq, const float* __restrict__ bk,
                                const float* __restrict__ bv) {
    int t = blockIdx.x * blockDim.x + threadIdx.x;
    if (t < CD*3*CD) {
        int row = t / (3*CD), col = t % (3*CD);
        int sel = col >> 7, c = col & (CD-1);
        const float* W = (sel == 0) ? Wq : (sel == 1) ? Wk : Wv;
        g_wqkv[t] = W[row*CD + c];
    }
    if (t < 3*CD) {
        int sel = t >> 7, c = t & (CD-1);
        const float* bb = (sel == 0) ? bq : (sel == 1) ? bk : bv;
        g_bqkv[t] = bb[c];
    }
}

// ---------------- RoPE (layer 0 only) ---------------------------------------
__global__ void rope_kernel(float* __restrict__ qkv, const float* __restrict__ pos) {
    int idx = blockIdx.x * blockDim.x + threadIdx.x;
    if (idx >= CM * 64) return;
    int p = idx & 63;
    int t = idx >> 6;
    int group = p >> 5;
    int fidx  = p & 31;
    float freq = 3.14159265358979324f * (float)(fidx + 1);
    float ang = pos[t*2 + group] * freq;
    float sv, cv;
    sincosf(ang, &sv, &cv);
    int qb = t*3*CD + (p << 1);
    float q0 = qkv[qb], q1 = qkv[qb+1];
    qkv[qb]   = cv*q0 - sv*q1;
    qkv[qb+1] = cv*q1 + sv*q0;
    int kb = qb + CD;
    float k0 = qkv[kb], k1 = qkv[kb+1];
    qkv[kb]   = cv*k0 - sv*k1;
    qkv[kb+1] = cv*k1 + sv*k0;
}

// ---------------- tensor-core GEMM (3xTF32): C = A@W + bias [+resid][relu] --
// CTA tile 128x64, BK=32, 8 warps (4m x 2n), warp tile 32x32 (2x4 mma tiles).
// smem: A [m][k] stride 36 (frag addr = 4g+t mod 32, conflict-free)
//       B [k][n] stride 72 (frag addr = 8t+g mod 32, conflict-free)
#define AS_STR 36
#define BS_STR 72
#define SM_AHI 0
#define SM_ALO (128*AS_STR)
#define SM_BHI (2*128*AS_STR)
#define SM_BLO (2*128*AS_STR + 32*BS_STR)
#define GEMM_SMEM ((2*128*AS_STR + 2*32*BS_STR)*4)

__global__ void __launch_bounds__(256)
gemm_tc_kernel(const float* __restrict__ A, const float* __restrict__ W,
               const float* __restrict__ bias, const float* __restrict__ resid,
               float* __restrict__ C, int M, int K, int Nout, int relu) {
    extern __shared__ float sm[];
    float* As_hi = sm + SM_AHI;
    float* As_lo = sm + SM_ALO;
    float* Bs_hi = sm + SM_BHI;
    float* Bs_lo = sm + SM_BLO;

    int tid = threadIdx.x;
    int lane = tid & 31, warp = tid >> 5;
    int wm = warp & 3, wn = warp >> 2;       // 4x2 warp grid
    int m_w = wm*32, n_w = wn*32;
    int g = lane >> 2, t = lane & 3;

    int bm0 = blockIdx.x * 128, bn0 = blockIdx.y * 64;

    float acc[2][4][4];
    #pragma unroll
    for (int i = 0; i < 2; ++i)
        #pragma unroll
        for (int j = 0; j < 4; ++j)
            #pragma unroll
            for (int u = 0; u < 4; ++u) acc[i][j][u] = 0.f;

    for (int k0 = 0; k0 < K; k0 += 32) {
        __syncthreads();
        // stage A tile 128x32 (1024 float4s / 256 threads = 4 each)
        #pragma unroll
        for (int it = 0; it < 4; ++it) {
            int f = tid + it*256;
            int row = f >> 3, c4 = (f & 7) << 2;
            float4 ga = *(const float4*)&A[(bm0 + row)*K + k0 + c4];
            float4 h4, l4;
            tf32split(ga.x, h4.x, l4.x);
            tf32split(ga.y, h4.y, l4.y);
            tf32split(ga.z, h4.z, l4.z);
            tf32split(ga.w, h4.w, l4.w);
            *(float4*)&As_hi[row*AS_STR + c4] = h4;
            *(float4*)&As_lo[row*AS_STR + c4] = l4;
        }
        // stage B tile 32x64 (512 float4s / 256 threads = 2 each)
        #pragma unroll
        for (int it = 0; it < 2; ++it) {
            int f = tid + it*256;
            int row = f >> 4, c4 = (f & 15) << 2;
            float4 gb = *(const float4*)&W[(k0 + row)*Nout + bn0 + c4];
            float4 h4, l4;
            tf32split(gb.x, h4.x, l4.x);
            tf32split(gb.y, h4.y, l4.y);
            tf32split(gb.z, h4.z, l4.z);
            tf32split(gb.w, h4.w, l4.w);
            *(float4*)&Bs_hi[row*BS_STR + c4] = h4;
            *(float4*)&Bs_lo[row*BS_STR + c4] = l4;
        }
        __syncthreads();

        #pragma unroll
        for (int k8 = 0; k8 < 32; k8 += 8) {
            unsigned ah[2][4], al[2][4];
            #pragma unroll
            for (int mt = 0; mt < 2; ++mt) {
                int base = (m_w + mt*16 + g)*AS_STR + k8 + t;
                ah[mt][0] = __float_as_uint(As_hi[base]);
                ah[mt][1] = __float_as_uint(As_hi[base + 8*AS_STR]);
                ah[mt][2] = __float_as_uint(As_hi[base + 4]);
                ah[mt][3] = __float_as_uint(As_hi[base + 8*AS_STR + 4]);
                al[mt][0] = __float_as_uint(As_lo[base]);
                al[mt][1] = __float_as_uint(As_lo[base + 8*AS_STR]);
                al[mt][2] = __float_as_uint(As_lo[base + 4]);
                al[mt][3] = __float_as_uint(As_lo[base + 8*AS_STR + 4]);
            }
            unsigned bh[4][2], bl[4][2];
            #pragma unroll
            for (int nt = 0; nt < 4; ++nt) {
                int base = (k8 + t)*BS_STR + n_w + nt*8 + g;
                bh[nt][0] = __float_as_uint(Bs_hi[base]);
                bh[nt][1] = __float_as_uint(Bs_hi[base + 4*BS_STR]);
                bl[nt][0] = __float_as_uint(Bs_lo[base]);
                bl[nt][1] = __float_as_uint(Bs_lo[base + 4*BS_STR]);
            }
            #pragma unroll
            for (int mt = 0; mt < 2; ++mt)
                #pragma unroll
                for (int nt = 0; nt < 4; ++nt) {
                    mma_tf32(acc[mt][nt], al[mt], bh[nt]);
                    mma_tf32(acc[mt][nt], ah[mt], bl[nt]);
                    mma_tf32(acc[mt][nt], ah[mt], bh[nt]);
                }
        }
    }

    // epilogue
    #pragma unroll
    for (int mt = 0; mt < 2; ++mt) {
        #pragma unroll
        for (int nt = 0; nt < 4; ++nt) {
            int row0 = bm0 + m_w + mt*16 + g;
            int col  = bn0 + n_w + nt*8 + 2*t;
            float2 bv = *(const float2*)&bias[col];
            float2 r0, r1;
            r0.x = acc[mt][nt][0] + bv.x;  r0.y = acc[mt][nt][1] + bv.y;
            r1.x = acc[mt][nt][2] + bv.x;  r1.y = acc[mt][nt][3] + bv.y;
            if (resid) {
                float2 v0 = *(const float2*)&resid[row0*Nout + col];
                float2 v1 = *(const float2*)&resid[(row0+8)*Nout + col];
                r0.x += v0.x; r0.y += v0.y;
                r1.x += v1.x; r1.y += v1.y;
            }
            if (relu) {
                r0.x = fmaxf(r0.x, 0.f); r0.y = fmaxf(r0.y, 0.f);
                r1.x = fmaxf(r1.x, 0.f); r1.y = fmaxf(r1.y, 0.f);
            }
            *(float2*)&C[row0*Nout + col]     = r0;
            *(float2*)&C[(row0+8)*Nout + col] = r1;
        }
    }
}

// ---------------- attention: candidate-list flash with f32x2 + j-split ------
// grid (NC2, 4 qtiles, CB*2 jhalf); 64 threads = 16 slots x 4 heads.
#define SROW 132
__global__ void __launch_bounds__(64)
attn_kernel(const float* __restrict__ qkv, const float* __restrict__ pos,
            const float* __restrict__ sqv) {
    __shared__ float  Ks[32*SROW];
    __shared__ float  Vs[32*SROW];
    __shared__ float2 Ps[32];
    __shared__ float  Ss[32];

    int cell = blockIdx.x, qt = blockIdx.y;
    int b = blockIdx.z >> 1, jh = blockIdx.z & 1;
    int cidx = b*NC2 + cell;
    int cstart = g_cstart[b][cell];
    int ccount = g_cstart[b][cell+1] - cstart;
    if (qt*16 >= ccount) return;

    int ncand = g_ncand[cidx];
    const int* cand = &g_cand[cidx*CAND_CAP];
    int half0 = ncand >> 1;
    int jstart = jh ? half0 : 0;
    int jend   = jh ? ncand : half0;

    int tid  = threadIdx.x;
    int slot = tid & 15;
    int head = tid >> 4;

    const float scale = 0.17677669529663687f;  // 1/sqrt(32)
    const float R2 = 0.0625f;
    const float NEG_INF = -CUDART_INF_F;
    ull scale2 = fpack2(scale, scale);

    for (int q0 = qt*16; q0 < ccount; q0 += 64) {
        bool active = (q0 + slot) < ccount;
        int qidx = active ? (q0 + slot) : 0;
        int qi = g_ord[b][cstart + qidx];
        int t = b*CN + qi;

        ull qr2[16];
        const ulonglong2* qp = (const ulonglong2*)&qkv[t*3*CD + head*CHD];
        #pragma unroll
        for (int u = 0; u < 8; ++u) {
            ulonglong2 qq = qp[u];
            qr2[2*u]   = fmul2(qq.x, scale2);
            qr2[2*u+1] = fmul2(qq.y, scale2);
        }
        float2 pi  = ((const float2*)pos)[t];
        float  sqi = sqv[t];

        float m = -1e30f, l = 0.f;
        ull acc2[16];
        #pragma unroll
        for (int u = 0; u < 16; ++u) acc2[u] = 0ull;

        for (int j0 = jstart; j0 < jend; j0 += 32) {
            __syncthreads();
            {
                int r = tid >> 1, half = tid & 1;
                int src = j0 + r;
                float4* kd = (float4*)&Ks[r*SROW] + half*16;
                float4* vd = (float4*)&Vs[r*SROW] + half*16;
                if (src < jend) {
                    int tj = b*CN + cand[src];
                    const float4* kp = (const float4*)&qkv[tj*3*CD + CD]   + half*16;
                    const float4* vp = (const float4*)&qkv[tj*3*CD + 2*CD] + half*16;
                    #pragma unroll
                    for (int u = 0; u < 16; ++u) { kd[u] = kp[u]; vd[u] = vp[u]; }
                    if (half == 0) { Ps[r] = ((const float2*)pos)[tj]; Ss[r] = sqv[tj]; }
                } else {
                    float4 z = make_float4(0.f,0.f,0.f,0.f);
                    #pragma unroll
                    for (int u = 0; u < 16; ++u) { kd[u] = z; vd[u] = z; }
                    if (half == 0) { Ps[r] = make_float2(0.f,0.f); Ss[r] = CUDART_INF_F; }
                }
            }
            __syncthreads();

            for (int j = 0; j < 32; ++j) {
                float2 pj = Ps[j];
                float d2 = sqi + Ss[j] - 2.f*(pi.x*pj.x + pi.y*pj.y);
                bool inw = (d2 <= R2);
                if (__ballot_sync(0xFFFFFFFFu, inw) == 0u) continue;

                const ulonglong2* kr = (const ulonglong2*)&Ks[j*SROW + (head<<5)];
                ull sa = 0ull, sb = 0ull;
                #pragma unroll
                for (int u = 0; u < 4; ++u) {
                    ulonglong2 k0v = kr[2*u], k1v = kr[2*u+1];
                    sa = ffma2(qr2[4*u],   k0v.x, sa);
                    sb = ffma2(qr2[4*u+1], k0v.y, sb);
                    sa = ffma2(qr2[4*u+2], k1v.x, sa);
                    sb = ffma2(qr2[4*u+3], k1v.y, sb);
                }
                float sl, sh, s;
                funpack2(fadd2(sa, sb), sl, sh);
                s = inw ? (sl + sh) : NEG_INF;

                if (s > m) {
                    float alpha = __expf(m - s);
                    m = s;
                    l *= alpha;
                    ull alpha2 = fpack2(alpha, alpha);
                    #pragma unroll
                    for (int u = 0; u < 16; ++u) acc2[u] = fmul2(acc2[u], alpha2);
                }
                float pb = __expf(s - m);
                l += pb;
                ull pb2 = fpack2(pb, pb);
                const ulonglong2* vr = (const ulonglong2*)&Vs[j*SROW + (head<<5)];
                #pragma unroll
                for (int u = 0; u < 8; ++u) {
                    ulonglong2 vv = vr[u];
                    acc2[2*u]   = ffma2(pb2, vv.x, acc2[2*u]);
                    acc2[2*u+1] = ffma2(pb2, vv.y, acc2[2*u+1]);
                }
            }
        }

        if (active) {
            int pidx = (jh*CM + t)*CH + head;
            g_pm[pidx] = m;
            g_pl[pidx] = l;
            ulonglong2* ap = (ulonglong2*)&g_pacc[pidx*32];
            #pragma unroll
            for (int u = 0; u < 8; ++u) {
                ulonglong2 w; w.x = acc2[2*u]; w.y = acc2[2*u+1];
                ap[u] = w;
            }
        }
    }
}

// ---------------- merge two attention halves, normalize, write o -----------
__global__ void merge_kernel(float* __restrict__ o) {
    int idx = blockIdx.x * blockDim.x + threadIdx.x;   // CM*CH*4
    if (idx >= CM*CH*4) return;
    int q8 = idx & 3;
    int h  = (idx >> 2) & 3;
    int t  = idx >> 4;
    int i0 = t*CH + h;
    int i1 = (CM + t)*CH + h;
    float m0 = g_pm[i0], m1 = g_pm[i1];
    float l0 = g_pl[i0], l1 = g_pl[i1];
    float m = fmaxf(m0, m1);
    float f0 = __expf(m0 - m), f1 = __expf(m1 - m);
    float inv = 1.f / (l0*f0 + l1*f1);
    f0 *= inv; f1 *= inv;
    const float4* a0 = (const float4*)&g_pacc[i0*32 + q8*8];
    const float4* a1 = (const float4*)&g_pacc[i1*32 + q8*8];
    float4* op = (float4*)&o[t*CD + h*CHD + q8*8];
    #pragma unroll
    for (int u = 0; u < 2; ++u) {
        float4 x0 = a0[u], x1 = a1[u];
        float4 r;
        r.x = x0.x*f0 + x1.x*f1;
        r.y = x0.y*f0 + x1.y*f1;
        r.z = x0.z*f0 + x1.z*f1;
        r.w = x0.w*f0 + x1.w*f1;
        op[u] = r;
    }
}

// ---------------- launch ----------------------------------------------------
extern "C" void kernel_launch(void* const* d_in, const int* in_sizes, int n_in,
                              void* d_out, int out_size) {
    const float* x    = (const float*)d_in[0];
    const float* pos  = (const float*)d_in[1];
    const float* Wq_w = (const float*)d_in[2];
    const float* Wq_b = (const float*)d_in[3];
    const float* Wk_w = (const float*)d_in[4];
    const float* Wk_b = (const float*)d_in[5];
    const float* Wv_w = (const float*)d_in[6];
    const float* Wv_b = (const float*)d_in[7];
    const float* Wo_w = (const float*)d_in[8];
    const float* Wo_b = (const float*)d_in[9];
    const float* n1_g = (const float*)d_in[10];
    const float* n1_b = (const float*)d_in[11];
    const float* n2_g = (const float*)d_in[12];
    const float* n2_b = (const float*)d_in[13];
    const float* l1_w = (const float*)d_in[14];
    const float* l1_b = (const float*)d_in[15];
    const float* l2_w = (const float*)d_in[16];
    const float* l2_b = (const float*)d_in[17];
    float* out = (float*)d_out;

    float *gx, *gxn, *gqkv, *go, *ghid, *gmu, *grstd, *gsq, *gwqkv, *gbqkv;
    double* gpart;
    cudaGetSymbolAddress((void**)&gx,    g_x);
    cudaGetSymbolAddress((void**)&gxn,   g_xn);
    cudaGetSymbolAddress((void**)&gqkv,  g_qkv);
    cudaGetSymbolAddress((void**)&go,    g_o);
    cudaGetSymbolAddress((void**)&ghid,  g_hid);
    cudaGetSymbolAddress((void**)&gpart, g_part);
    cudaGetSymbolAddress((void**)&gmu,   g_mu);
    cudaGetSymbolAddress((void**)&grstd, g_rstd);
    cudaGetSymbolAddress((void**)&gsq,   g_sq);
    cudaGetSymbolAddress((void**)&gwqkv, g_wqkv);
    cudaGetSymbolAddress((void**)&gbqkv, g_bqkv);

    cudaFuncSetAttribute(gemm_tc_kernel,
                         cudaFuncAttributeMaxDynamicSharedMemorySize, GEMM_SMEM);

    copy_kernel<<<(CM*CD + 255)/256, 256>>>(x, gx, CM*CD);

    // spatial binning + per-cell candidate lists (once; shared by both layers)
    zero_cnt_kernel<<<1, CB*NC2>>>();
    hist_kernel<<<(CM + 255)/256, 256>>>(pos);
    scan_kernel<<<CB, NC2>>>();
    scatter_kernel<<<(CM + 255)/256, 256>>>();
    build_cands_kernel<<<CB*NC2/4, 128>>>(pos);

    dim3 gP(CM/128, CD/64);          // N=128 outputs
    dim3 gQKV(CM/128, 3*CD/64);      // N=384 fused qkv
    dim3 gF(CM/128, 2*CD/64);        // N=256 FFN hidden

    for (int i = 0; i < 2; ++i) {
        // --- attention block ---
        bn_stats_kernel<<<64, 128>>>(gx, gpart);
        bn_finalize_kernel<<<1, 128>>>(gpart, gmu, grstd);
        bn_apply_kernel<<<(CM*CD + 255)/256, 256>>>(gx, n1_g + i*CD, n1_b + i*CD, gmu, grstd, gxn);

        pack_qkv_kernel<<<(CD*3*CD + 255)/256, 256>>>(Wq_w + i*CD*CD, Wk_w + i*CD*CD, Wv_w + i*CD*CD,
                                                      Wq_b + i*CD, Wk_b + i*CD, Wv_b + i*CD);
        gemm_tc_kernel<<<gQKV, 256, GEMM_SMEM>>>(gxn, gwqkv, gbqkv, nullptr, gqkv, CM, CD, 3*CD, 0);

        if (i == 0)
            rope_kernel<<<(CM*64 + 255)/256, 256>>>(gqkv, pos);

        attn_kernel<<<dim3(NC2, 4, CB*2), 64>>>(gqkv, pos, gsq);
        merge_kernel<<<(CM*CH*4 + 255)/256, 256>>>(go);

        gemm_tc_kernel<<<gP, 256, GEMM_SMEM>>>(go, Wo_w + i*CD*CD, Wo_b + i*CD, gx, gx, CM, CD, CD, 0);

        // --- FFN block ---
        bn_stats_kernel<<<64, 128>>>(gx, gpart);
        bn_finalize_kernel<<<1, 128>>>(gpart, gmu, grstd);
        bn_apply_kernel<<<(CM*CD + 255)/256, 256>>>(gx, n2_g + i*CD, n2_b + i*CD, gmu, grstd, gxn);

        gemm_tc_kernel<<<gF, 256, GEMM_SMEM>>>(gxn, l1_w + i*CD*2*CD, l1_b + i*2*CD, nullptr, ghid, CM, CD, 2*CD, 1);

        float* dst = (i == 1) ? out : gx;
        gemm_tc_kernel<<<gP, 256, GEMM_SMEM>>>(ghid, l2_w + i*2*CD*CD, l2_b + i*CD, gx, dst, CM, 2*CD, CD, 0);
    }
}